// round 15
// baseline (speedup 1.0000x reference)
#include <cuda_runtime.h>
#include <cstdint>
#include <math.h>

#define N_JOINTS 50
#define ROW 150
#define THREADS 128
#define WARPS_PER_CTA 4
#define TOTAL_ROWS (128 * 1024)
#define WTILE_ROWS 2
#define WTILE_ELEMS (WTILE_ROWS * ROW)            // 300 floats per tensor
#define WTILE_VECS (WTILE_ELEMS / 4)              // 75 float4
#define N_WTILES (TOTAL_ROWS / WTILE_ROWS)        // 65536
#define NBUF 3
#define GRID (148 * 7)                             // 1036 CTAs, 7/SM
#define GWARPS (GRID * WARPS_PER_CTA)             // 4144
#define DOT_FLOOR 1e-30f

// Per-block partials, fully overwritten every launch.
__device__ float g_part_abs[GRID];
__device__ float g_part_cos[GRID];
// atomicInc wraps to 0 after GRID increments -> deterministic across replays.
__device__ unsigned int g_count = 0;

__device__ __forceinline__ void cp_async16(unsigned saddr, const void* gaddr) {
    asm volatile("cp.async.cg.shared.global [%0], [%1], 16;\n"
                 :: "r"(saddr), "l"(gaddr));
}
#define CP_COMMIT() asm volatile("cp.async.commit_group;\n" ::: "memory")
#define CP_WAIT2()  asm volatile("cp.async.wait_group 2;\n" ::: "memory")

__global__ __launch_bounds__(THREADS) void bone_loss_kernel(
    const float* __restrict__ preds,
    const float* __restrict__ targets,
    float* __restrict__ out)
{
    // Warp-private TRIPLE buffers: prefetch distance 2, no block sync in loop.
    __shared__ float sp[WARPS_PER_CTA][NBUF][WTILE_ELEMS];
    __shared__ float st[WARPS_PER_CTA][NBUF][WTILE_ELEMS];
    __shared__ float s_abs[WARPS_PER_CTA];
    __shared__ float s_cos[WARPS_PER_CTA];
    __shared__ bool s_last;

    const int tid = threadIdx.x;
    const int wid = tid >> 5;
    const int lid = tid & 31;

    float abs_sum = 0.0f;
    float cos_sum = 0.0f;

    const int wt0 = blockIdx.x * WARPS_PER_CTA + wid;   // this warp's first tile

    // prologue: stage tiles wt0 (buf0) and wt0+GWARPS (buf1), two groups
    #pragma unroll
    for (int s = 0; s < 2; s++) {
        const int t = wt0 + s * GWARPS;
        if (t < N_WTILES) {
            const float4* pg = (const float4*)preds   + (long long)t * WTILE_VECS;
            const float4* tg = (const float4*)targets + (long long)t * WTILE_VECS;
            unsigned sp_s = (unsigned)__cvta_generic_to_shared(&sp[wid][s][0]);
            unsigned st_s = (unsigned)__cvta_generic_to_shared(&st[wid][s][0]);
            for (int i = lid; i < WTILE_VECS; i += 32) {
                cp_async16(sp_s + i * 16, pg + i);
                cp_async16(st_s + i * 16, tg + i);
            }
        }
        CP_COMMIT();
    }

    int buf = 0;       // buffer holding current tile
    int sbuf = 2;      // buffer to stage into (distance-2 tile)
    for (int wt = wt0; wt < N_WTILES; wt += GWARPS) {
        // ---- stage tile wt + 2*GWARPS into sbuf ----
        const int next2 = wt + 2 * GWARPS;
        if (next2 < N_WTILES) {
            const float4* pg = (const float4*)preds   + (long long)next2 * WTILE_VECS;
            const float4* tg = (const float4*)targets + (long long)next2 * WTILE_VECS;
            unsigned sp_s = (unsigned)__cvta_generic_to_shared(&sp[wid][sbuf][0]);
            unsigned st_s = (unsigned)__cvta_generic_to_shared(&st[wid][sbuf][0]);
            for (int i = lid; i < WTILE_VECS; i += 32) {
                cp_async16(sp_s + i * 16, pg + i);
                cp_async16(st_s + i * 16, tg + i);
            }
        }
        CP_COMMIT();          // one group per iteration (possibly empty)
        CP_WAIT2();           // all but 2 newest groups done -> current tile ready
        __syncwarp();

        const float* cp = sp[wid][buf];
        const float* ct = st[wid][buf];

        // ---- fused pass: 2 rows = 100 bones; fold joint-a L1 term in ----
        #pragma unroll
        for (int it = 0; it < 4; it++) {
            const int idx = lid + it * 32;
            if (idx < 2 * N_JOINTS) {
                const int r  = (idx >= N_JOINTS) ? 1 : 0;
                const int bi = idx - r * N_JOINTS;
                const int nj = (bi + 1 == N_JOINTS) ? 0 : bi + 1;
                const int roff = r * ROW;
                const int a = roff + 3 * bi;
                const int b = roff + 3 * nj;

                float pa0 = cp[a], pa1 = cp[a + 1], pa2 = cp[a + 2];
                float ta0 = ct[a], ta1 = ct[a + 1], ta2 = ct[a + 2];
                float pb0 = cp[b], pb1 = cp[b + 1], pb2 = cp[b + 2];
                float tb0 = ct[b], tb1 = ct[b + 1], tb2 = ct[b + 2];

                abs_sum += fabsf(pa0 - ta0) + fabsf(pa1 - ta1) + fabsf(pa2 - ta2);

                float pd0 = pa0 - pb0, pd1 = pa1 - pb1, pd2 = pa2 - pb2;
                float td0 = ta0 - tb0, td1 = ta1 - tb1, td2 = ta2 - tb2;

                float pdot  = fmaf(pd0, pd0, fmaf(pd1, pd1, pd2 * pd2));
                float tdot  = fmaf(td0, td0, fmaf(td1, td1, td2 * td2));
                float ptdot = fmaf(pd0, td0, fmaf(pd1, td1, pd2 * td2));

                float pinv = rsqrtf(fmaxf(pdot, DOT_FLOOR));
                float tinv = rsqrtf(fmaxf(tdot, DOT_FLOOR));
                cos_sum += (ptdot * pinv) * tinv;
            }
        }
        __syncwarp();         // all lanes done reading buf before its reuse
        buf  = (buf  == NBUF - 1) ? 0 : buf + 1;
        sbuf = (sbuf == NBUF - 1) ? 0 : sbuf + 1;
    }

    // ---- warp + block reduction ----
    #pragma unroll
    for (int off = 16; off > 0; off >>= 1) {
        abs_sum += __shfl_down_sync(0xFFFFFFFFu, abs_sum, off);
        cos_sum += __shfl_down_sync(0xFFFFFFFFu, cos_sum, off);
    }
    if (lid == 0) { s_abs[wid] = abs_sum; s_cos[wid] = cos_sum; }
    __syncthreads();

    // ---- publish partial, detect last block ----
    if (tid == 0) {
        float ba = 0.0f, bc = 0.0f;
        #pragma unroll
        for (int w = 0; w < WARPS_PER_CTA; w++) { ba += s_abs[w]; bc += s_cos[w]; }
        g_part_abs[blockIdx.x] = ba;
        g_part_cos[blockIdx.x] = bc;
        __threadfence();
        unsigned int v = atomicInc(&g_count, GRID - 1); // wraps to 0 on last
        s_last = (v == GRID - 1);
    }
    __syncthreads();

    // ---- last block: final reduction over all partials (L2-resident) ----
    if (s_last) {
        double a = 0.0, c = 0.0;
        for (int i = tid; i < GRID; i += THREADS) {
            a += (double)g_part_abs[i];
            c += (double)g_part_cos[i];
        }
        #pragma unroll
        for (int off = 16; off > 0; off >>= 1) {
            a += __shfl_down_sync(0xFFFFFFFFu, a, off);
            c += __shfl_down_sync(0xFFFFFFFFu, c, off);
        }
        __shared__ double sh_a[WARPS_PER_CTA], sh_c[WARPS_PER_CTA];
        if (lid == 0) { sh_a[wid] = a; sh_c[wid] = c; }
        __syncthreads();
        if (tid == 0) {
            double ta = 0.0, tc = 0.0;
            #pragma unroll
            for (int w = 0; w < WARPS_PER_CTA; w++) { ta += sh_a[w]; tc += sh_c[w]; }
            const double NB = (double)TOTAL_ROWS * (double)N_JOINTS; // bones
            const double N  = (double)TOTAL_ROWS * (double)ROW;      // elements
            double sq_total = 2.0 * NB - 2.0 * tc;
            out[0] = (float)((ta / N + 0.1 * (sq_total / N)) * 0.1);
        }
    }
}

extern "C" void kernel_launch(void* const* d_in, const int* in_sizes, int n_in,
                              void* d_out, int out_size) {
    const float* preds   = (const float*)d_in[0];
    const float* targets = (const float*)d_in[1];
    float* out = (float*)d_out;

    bone_loss_kernel<<<GRID, THREADS>>>(preds, targets, out);
}